// round 2
// baseline (speedup 1.0000x reference)
#include <cuda_runtime.h>
#include <cuda_bf16.h>

// Output layout (float32 elements, concatenated in reference return order):
//   [0, B*NP*FEAT)      batch          (B, NP, FEAT)
//   [+, B*NP)           proposal_mask  (B, NP)
//   [+, P)              scores_pred    (P,)
//   [+, B*NP*K)         proposal_ious  (B, NP, K)
//   [+, P*N_POINTS)     proposals_pred (P, N_POINTS)

static constexpr int NUM_PROPOSAL = 256;

// ---------------------------------------------------------------------------
// Small per-proposal kernel: single block of P threads.
// ---------------------------------------------------------------------------
__global__ void refnet_small_kernel(
    const float* __restrict__ scores,   // (P,1)
    const float* __restrict__ feats,    // (P,FEAT)
    const float* __restrict__ ious,     // (P,K)
    const int*   __restrict__ pidx,     // (M,2) int32
    const int*   __restrict__ poff,     // (P+1,) int32
    const int*   __restrict__ boff,     // (B+1,) int32
    float* __restrict__ out,
    int P, int FEAT, int K, int B,
    long long off_batch, long long off_mask, long long off_scores, long long off_ious)
{
    __shared__ int b_arr[1024];
    int p = threadIdx.x;
    if (p >= P) return;

    // sigmoid
    float s = scores[p];
    out[off_scores + p] = 1.0f / (1.0f + expf(-s));

    // first point of proposal p -> batch index (searchsorted right - 1)
    int o = poff[p];
    int first_pt = pidx[2 * o + 1];
    int b = 0;
    for (int i = 1; i <= B; ++i) {
        if (boff[i] <= first_pt) b = i;   // last i with boff[i] <= first_pt
    }
    b_arr[p] = b;
    __syncthreads();

    // slot = number of earlier proposals in the same batch (stable rank)
    int slot = 0;
    for (int q = 0; q < p; ++q) slot += (b_arr[q] == b);

    long long base = (long long)b * NUM_PROPOSAL + slot;
    out[off_mask + base] = 1.0f;

    const float* fsrc = feats + (long long)p * FEAT;
    float* fdst = out + off_batch + base * FEAT;
    for (int i = 0; i < FEAT; ++i) fdst[i] = fsrc[i];

    const float* isrc = ious + (long long)p * K;
    float* idst = out + off_ious + base * K;
    for (int i = 0; i < K; ++i) idst[i] = isrc[i];
}

// ---------------------------------------------------------------------------
// Scatter ones into proposals_pred. One thread per (pid, ptid) pair.
// Rows are 8B-aligned int32 pairs -> single 64-bit load.
// ---------------------------------------------------------------------------
__global__ void refnet_scatter_kernel(
    const int2* __restrict__ pidx,   // (M) pairs
    float* __restrict__ pp,          // proposals_pred region base
    int M, long long n_points)
{
    int i = blockIdx.x * blockDim.x + threadIdx.x;
    if (i >= M) return;
    int2 v = pidx[i];
    pp[(long long)v.x * n_points + (long long)v.y] = 1.0f;
}

extern "C" void kernel_launch(void* const* d_in, const int* in_sizes, int n_in,
                              void* d_out, int out_size) {
    const float* scores = (const float*)d_in[0];
    const float* feats  = (const float*)d_in[1];
    const float* ious   = (const float*)d_in[2];
    const int*   pidx   = (const int*)d_in[3];
    const int*   poff   = (const int*)d_in[4];
    const int*   boff   = (const int*)d_in[5];

    int P    = in_sizes[0];               // 256  (scores is (P,1))
    int FEAT = in_sizes[1] / P;           // 16
    int K    = in_sizes[2] / P;           // 32
    int M    = in_sizes[3] / 2;           // 1048576
    int B    = in_sizes[5] - 1;           // 4

    long long off_batch  = 0;
    long long off_mask   = off_batch + (long long)B * NUM_PROPOSAL * FEAT;
    long long off_scores = off_mask  + (long long)B * NUM_PROPOSAL;
    long long off_ious   = off_scores + P;
    long long off_pp     = off_ious  + (long long)B * NUM_PROPOSAL * K;
    long long n_points   = ((long long)out_size - off_pp) / P;

    float* out = (float*)d_out;

    // 1) Zero everything (memset hits near-peak HBM write BW; int/float zero identical)
    cudaMemsetAsync(d_out, 0, (size_t)out_size * sizeof(float), 0);

    // 2) Small per-proposal work (one block)
    refnet_small_kernel<<<1, P>>>(scores, feats, ious, pidx, poff, boff, out,
                                  P, FEAT, K, B,
                                  off_batch, off_mask, off_scores, off_ious);

    // 3) Scatter ones into proposals_pred
    int threads = 512;
    int blocks = (M + threads - 1) / threads;
    refnet_scatter_kernel<<<blocks, threads>>>((const int2*)pidx,
                                               out + off_pp, M, n_points);
}